// round 2
// baseline (speedup 1.0000x reference)
#include <cuda_runtime.h>

// ---------------------------------------------------------------------------
// MultiLoss_KLD: mse over cols {0,55,56,57} + blockwise cross-entropy +
// KL divergence of sex-conditioned histograms of data_encoded[:, :10].
// label_true is mathematically unused (comb[:, :10] and comb[:,11] are all
// data_encoded columns since data_encoded has 12 cols).
// ---------------------------------------------------------------------------

static constexpr int NC = 99;   // columns of decoded/true
static constexpr int TR = 32;   // rows per tile in k_main

// Accumulators (device globals: no allocation allowed)
__device__ double   g_mse_sum;
__device__ double   g_ce_sum;
__device__ unsigned g_minmap[10];
__device__ unsigned g_maxmap[10];
__device__ int      g_hist[200];   // [2][10][10]: (sex*10 + feature)*10 + bin
__device__ int      g_cnt[2];      // [m_count, f_count]

__constant__ int c_bs[8] = {1, 8, 24, 31, 45, 51, 53, 58};
__constant__ int c_be[8] = {8, 24, 31, 45, 51, 53, 55, 99};
__constant__ int c_cc[4] = {0, 55, 56, 57};

// Monotone float <-> uint mapping for atomicMin/Max on floats
__device__ __forceinline__ unsigned fmap(float f) {
    unsigned u = __float_as_uint(f);
    return (u & 0x80000000u) ? ~u : (u | 0x80000000u);
}
__device__ __forceinline__ float funmap(unsigned m) {
    unsigned u = (m & 0x80000000u) ? (m & 0x7FFFFFFFu) : ~m;
    return __uint_as_float(u);
}

__global__ void k_init() {
    int t = threadIdx.x;
    if (t == 0) { g_mse_sum = 0.0; g_ce_sum = 0.0; g_cnt[0] = 0; g_cnt[1] = 0; }
    if (t < 200) g_hist[t] = 0;
    if (t >= 200 && t < 210) g_minmap[t - 200] = 0xFFFFFFFFu;
    if (t >= 210 && t < 220) g_maxmap[t - 210] = 0u;
}

// ---------------------------------------------------------------------------
// k_main: per 32-row tile — CE (warp w = CE block w, lane = row), MSE,
// and per-column min/max of the 10 KLD features.
// ---------------------------------------------------------------------------
__global__ void __launch_bounds__(256) k_main(const float* __restrict__ dec,
                                              const float* __restrict__ tru,
                                              const float* __restrict__ enc,
                                              int B) {
    __shared__ alignas(16) float sD[TR * NC];
    __shared__ alignas(16) float sT[TR * NC];
    __shared__ alignas(16) float sE[TR * 12];
    __shared__ float wsum[16];

    int tid = threadIdx.x;
    long long row0 = (long long)blockIdx.x * TR;
    int nrows = (int)(((long long)B - row0) < TR ? ((long long)B - row0) : TR);

    if (nrows == TR) {
        const float4* gD = (const float4*)(dec + row0 * NC);
        const float4* gT = (const float4*)(tru + row0 * NC);
        const float4* gE = (const float4*)(enc + row0 * 12);
        #pragma unroll 2
        for (int i = tid; i < TR * NC / 4; i += 256) {   // 792 float4 per array
            ((float4*)sD)[i] = gD[i];
            ((float4*)sT)[i] = gT[i];
        }
        if (tid < TR * 12 / 4) ((float4*)sE)[tid] = gE[tid];
    } else {
        for (int i = tid; i < nrows * NC; i += 256) {
            sD[i] = dec[row0 * NC + i];
            sT[i] = tru[row0 * NC + i];
        }
        for (int i = tid; i < nrows * 12; i += 256) sE[i] = enc[row0 * 12 + i];
    }
    __syncthreads();

    // --- cross entropy: warp (tid>>5) handles CE block (tid>>5), lane = row
    float acc = 0.f;
    {
        int r = tid & 31;
        int blk = tid >> 5;
        if (r < nrows) {
            int s = c_bs[blk], e = c_be[blk];
            const float* Dr = sD + r * NC;
            const float* Tr = sT + r * NC;
            float m = -3.402823466e38f;
            for (int c = s; c < e; ++c) m = fmaxf(m, Dr[c]);
            float sum = 0.f, dot = 0.f;
            for (int c = s; c < e; ++c) {
                sum += __expf(Dr[c] - m);
                dot += Tr[c] * Dr[c];
            }
            acc = (m + __logf(sum)) - dot;   // = -(sum onehot*logp) for this row/block
        }
    }

    // --- mse over 4 continuous cols (128 work items)
    float msea = 0.f;
    if (tid < TR * 4) {
        int r = tid >> 2;
        int c = c_cc[tid & 3];
        if (r < nrows) {
            float d = sD[r * NC + c] - sT[r * NC + c];
            msea = d * d;
        }
    }

    // --- per-column min/max of encoded[:, 0:10] (threads 0..19)
    if (tid < 20) {
        int c = (tid < 10) ? tid : (tid - 10);
        if (tid < 10) {
            float v = 3.402823466e38f;
            for (int r = 0; r < nrows; ++r) v = fminf(v, sE[r * 12 + c]);
            atomicMin(&g_minmap[c], fmap(v));
        } else {
            float v = -3.402823466e38f;
            for (int r = 0; r < nrows; ++r) v = fmaxf(v, sE[r * 12 + c]);
            atomicMax(&g_maxmap[c], fmap(v));
        }
    }

    // --- block reduce ce + mse, one double atomic each per CTA
    #pragma unroll
    for (int o = 16; o; o >>= 1) {
        acc  += __shfl_down_sync(0xffffffffu, acc,  o);
        msea += __shfl_down_sync(0xffffffffu, msea, o);
    }
    if ((tid & 31) == 0) { wsum[tid >> 5] = acc; wsum[8 + (tid >> 5)] = msea; }
    __syncthreads();
    if (tid == 0) {
        double ce = 0.0, mse = 0.0;
        #pragma unroll
        for (int i = 0; i < 8; ++i) { ce += (double)wsum[i]; mse += (double)wsum[8 + i]; }
        atomicAdd(&g_ce_sum, ce);
        atomicAdd(&g_mse_sum, mse);
    }
}

// ---------------------------------------------------------------------------
// k_hist: one thread per row; warp-aggregated shared histogram.
// ---------------------------------------------------------------------------
__global__ void __launch_bounds__(256) k_hist(const float* __restrict__ enc, int B) {
    __shared__ int hist[200];
    __shared__ int cnt[2];
    __shared__ float smn[10], swid[10];

    int tid = threadIdx.x;
    if (tid < 200) hist[tid] = 0;
    if (tid < 2) cnt[tid] = 0;
    if (tid >= 224 && tid < 234) {
        int c = tid - 224;
        float mn = funmap(g_minmap[c]);
        float mx = funmap(g_maxmap[c]);
        smn[c] = mn;
        swid[c] = fmaxf(mx - mn, 1e-12f);
    }
    __syncthreads();

    long long r = (long long)blockIdx.x * 256 + tid;
    bool valid = r < (long long)B;
    float x[12];
    #pragma unroll
    for (int i = 0; i < 12; ++i) x[i] = 0.f;
    if (valid) {
        const float4* row = (const float4*)(enc + r * 12);
        float4 a = row[0], b = row[1], c = row[2];
        x[0] = a.x; x[1] = a.y; x[2]  = a.z; x[3]  = a.w;
        x[4] = b.x; x[5] = b.y; x[6]  = b.z; x[7]  = b.w;
        x[8] = c.x; x[9] = c.y; x[10] = c.z; x[11] = c.w;
    }

    int s = (valid && x[11] == 1.0f) ? 1 : 0;   // sex: 1 -> f group, 0 -> m group
    unsigned bf = __ballot_sync(0xffffffffu, valid && s == 1);
    unsigned bv = __ballot_sync(0xffffffffu, valid);
    if ((tid & 31) == 0) {
        atomicAdd(&cnt[1], __popc(bf));
        atomicAdd(&cnt[0], __popc(bv) - __popc(bf));
    }

    #pragma unroll
    for (int i = 0; i < 10; ++i) {
        // replicate reference binning bit pattern: floor((x-mn)/width * 10), clip
        float f = (x[i] - smn[i]) / swid[i] * 10.0f;
        int idx = (int)floorf(f);
        idx = min(max(idx, 0), 9);
        int key = valid ? (s * 10 + idx) : (32 + (tid & 31));  // invalid lanes unique
        unsigned mask = __match_any_sync(0xffffffffu, key);
        if (valid && (tid & 31) == (__ffs(mask) - 1)) {
            atomicAdd(&hist[(s * 10 + i) * 10 + idx], __popc(mask));
        }
    }

    __syncthreads();
    if (tid < 200 && hist[tid] != 0) atomicAdd(&g_hist[tid], hist[tid]);
    if (tid < 2) atomicAdd(&g_cnt[tid], cnt[tid]);
}

// ---------------------------------------------------------------------------
// k_final: 100-bin KLD (double) + combine + write 4 outputs.
// ---------------------------------------------------------------------------
__global__ void k_final(float* __restrict__ out, int B) {
    double mc = g_cnt[0] > 0 ? (double)g_cnt[0] : 1.0;
    double fc = g_cnt[1] > 0 ? (double)g_cnt[1] : 1.0;
    double kld = 0.0;
    for (int j = 0; j < 100; ++j) {
        double p = (double)g_hist[j]       / mc;
        double q = (double)g_hist[100 + j] / fc;
        if (p > 0.0 && q > 0.0) kld += p * log(p / q);
    }
    float mse = (float)(g_mse_sum / (double)B);
    float ce  = (float)(g_ce_sum  / (double)B);
    float ak  = 0.5f * (float)kld;          // alpha = RATIO_KLD = 0.5
    float multi = 0.5f * (mse + ce) + ak;   // (1-alpha)*(mse+ce) + alpha*kld
    out[0] = multi;
    out[1] = mse;
    out[2] = ce;
    out[3] = ak;
}

extern "C" void kernel_launch(void* const* d_in, const int* in_sizes, int n_in,
                              void* d_out, int out_size) {
    (void)n_in; (void)out_size;
    const float* enc = (const float*)d_in[0];  // data_encoded [B,12]
    const float* dec = (const float*)d_in[1];  // data_decoded [B,99]
    const float* tru = (const float*)d_in[2];  // data_true    [B,99]
    // d_in[3] = label_true (unused), d_in[4] = batch_size (unused; derive B)
    int B = in_sizes[1] / NC;

    k_init<<<1, 256>>>();
    int tiles = (B + TR - 1) / TR;
    k_main<<<tiles, 256>>>(dec, tru, enc, B);
    int hb = (B + 255) / 256;
    k_hist<<<hb, 256>>>(enc, B);
    k_final<<<1, 1>>>((float*)d_out, B);
}

// round 4
// speedup vs baseline: 3.3046x; 3.3046x over previous
#include <cuda_runtime.h>

// ---------------------------------------------------------------------------
// MultiLoss_KLD: mse over cols {0,55,56,57} + blockwise cross-entropy +
// KL divergence of sex-conditioned histograms of data_encoded[:, :10].
// label_true is mathematically unused.
// ---------------------------------------------------------------------------

static constexpr int NC = 99;   // columns of decoded/true
static constexpr int TR = 32;   // rows per tile in k_main

// Accumulators (device globals: no allocation allowed)
__device__ double   g_mse_sum;
__device__ double   g_ce_sum;
__device__ unsigned g_minmap[10];
__device__ unsigned g_maxmap[10];
__device__ int      g_hist[200];   // [2][10][10]: (sex*10 + feature)*10 + bin
__device__ int      g_cnt[2];      // [m_count, f_count]

__constant__ int c_bs[8] = {1, 8, 24, 31, 45, 51, 53, 58};
__constant__ int c_be[8] = {8, 24, 31, 45, 51, 53, 55, 99};
__constant__ int c_cc[4] = {0, 55, 56, 57};

// Monotone float <-> uint mapping for atomicMin/Max on floats
__device__ __forceinline__ unsigned fmap(float f) {
    unsigned u = __float_as_uint(f);
    return (u & 0x80000000u) ? ~u : (u | 0x80000000u);
}
__device__ __forceinline__ float funmap(unsigned m) {
    unsigned u = (m & 0x80000000u) ? (m & 0x7FFFFFFFu) : ~m;
    return __uint_as_float(u);
}

__global__ void k_init() {
    int t = threadIdx.x;
    if (t == 0) { g_mse_sum = 0.0; g_ce_sum = 0.0; g_cnt[0] = 0; g_cnt[1] = 0; }
    if (t < 200) g_hist[t] = 0;
    if (t >= 200 && t < 210) g_minmap[t - 200] = 0xFFFFFFFFu;
    if (t >= 210 && t < 220) g_maxmap[t - 210] = 0u;
}

// ---------------------------------------------------------------------------
// k_main: per 32-row tile — CE (warp w = CE block w, lane = row), MSE,
// and per-column min/max of the 10 KLD features.
// ---------------------------------------------------------------------------
__global__ void __launch_bounds__(256) k_main(const float* __restrict__ dec,
                                              const float* __restrict__ tru,
                                              const float* __restrict__ enc,
                                              int B) {
    __shared__ alignas(16) float sD[TR * NC];
    __shared__ alignas(16) float sT[TR * NC];
    __shared__ alignas(16) float sE[TR * 12];
    __shared__ float wsum[16];

    int tid = threadIdx.x;
    long long row0 = (long long)blockIdx.x * TR;
    int nrows = (int)(((long long)B - row0) < TR ? ((long long)B - row0) : TR);

    if (nrows == TR) {
        const float4* gD = (const float4*)(dec + row0 * NC);
        const float4* gT = (const float4*)(tru + row0 * NC);
        const float4* gE = (const float4*)(enc + row0 * 12);
        #pragma unroll 2
        for (int i = tid; i < TR * NC / 4; i += 256) {   // 792 float4 per array
            ((float4*)sD)[i] = gD[i];
            ((float4*)sT)[i] = gT[i];
        }
        if (tid < TR * 12 / 4) ((float4*)sE)[tid] = gE[tid];
    } else {
        for (int i = tid; i < nrows * NC; i += 256) {
            sD[i] = dec[row0 * NC + i];
            sT[i] = tru[row0 * NC + i];
        }
        for (int i = tid; i < nrows * 12; i += 256) sE[i] = enc[row0 * 12 + i];
    }
    __syncthreads();

    // --- cross entropy: warp (tid>>5) handles CE block (tid>>5), lane = row
    float acc = 0.f;
    {
        int r = tid & 31;
        int blk = tid >> 5;
        if (r < nrows) {
            int s = c_bs[blk], e = c_be[blk];
            const float* Dr = sD + r * NC;
            const float* Tr = sT + r * NC;
            float m = -3.402823466e38f;
            for (int c = s; c < e; ++c) m = fmaxf(m, Dr[c]);
            float sum = 0.f, dot = 0.f;
            for (int c = s; c < e; ++c) {
                sum += __expf(Dr[c] - m);
                dot += Tr[c] * Dr[c];
            }
            acc = (m + __logf(sum)) - dot;   // = -(sum onehot*logp) for this row/block
        }
    }

    // --- mse over 4 continuous cols (128 work items)
    float msea = 0.f;
    if (tid < TR * 4) {
        int r = tid >> 2;
        int c = c_cc[tid & 3];
        if (r < nrows) {
            float d = sD[r * NC + c] - sT[r * NC + c];
            msea = d * d;
        }
    }

    // --- per-column min/max of encoded[:, 0:10] (threads 0..19)
    if (tid < 20) {
        int c = (tid < 10) ? tid : (tid - 10);
        if (tid < 10) {
            float v = 3.402823466e38f;
            for (int r = 0; r < nrows; ++r) v = fminf(v, sE[r * 12 + c]);
            atomicMin(&g_minmap[c], fmap(v));
        } else {
            float v = -3.402823466e38f;
            for (int r = 0; r < nrows; ++r) v = fmaxf(v, sE[r * 12 + c]);
            atomicMax(&g_maxmap[c], fmap(v));
        }
    }

    // --- block reduce ce + mse, one double atomic each per CTA
    #pragma unroll
    for (int o = 16; o; o >>= 1) {
        acc  += __shfl_down_sync(0xffffffffu, acc,  o);
        msea += __shfl_down_sync(0xffffffffu, msea, o);
    }
    if ((tid & 31) == 0) { wsum[tid >> 5] = acc; wsum[8 + (tid >> 5)] = msea; }
    __syncthreads();
    if (tid == 0) {
        double ce = 0.0, mse = 0.0;
        #pragma unroll
        for (int i = 0; i < 8; ++i) { ce += (double)wsum[i]; mse += (double)wsum[8 + i]; }
        atomicAdd(&g_ce_sum, ce);
        atomicAdd(&g_mse_sum, mse);
    }
}

// ---------------------------------------------------------------------------
// k_hist: one thread per row; warp-aggregated shared histogram.
// ---------------------------------------------------------------------------
__global__ void __launch_bounds__(256) k_hist(const float* __restrict__ enc, int B) {
    __shared__ int hist[200];
    __shared__ int cnt[2];
    __shared__ float smn[10], swid[10];

    int tid = threadIdx.x;
    if (tid < 200) hist[tid] = 0;
    if (tid < 2) cnt[tid] = 0;
    if (tid >= 224 && tid < 234) {
        int c = tid - 224;
        float mn = funmap(g_minmap[c]);
        float mx = funmap(g_maxmap[c]);
        smn[c] = mn;
        swid[c] = fmaxf(mx - mn, 1e-12f);
    }
    __syncthreads();

    long long r = (long long)blockIdx.x * 256 + tid;
    bool valid = r < (long long)B;
    float x[12];
    #pragma unroll
    for (int i = 0; i < 12; ++i) x[i] = 0.f;
    if (valid) {
        const float4* row = (const float4*)(enc + r * 12);
        float4 a = row[0], b = row[1], c = row[2];
        x[0] = a.x; x[1] = a.y; x[2]  = a.z; x[3]  = a.w;
        x[4] = b.x; x[5] = b.y; x[6]  = b.z; x[7]  = b.w;
        x[8] = c.x; x[9] = c.y; x[10] = c.z; x[11] = c.w;
    }

    int s = (valid && x[11] == 1.0f) ? 1 : 0;   // sex: 1 -> f group, 0 -> m group
    unsigned bf = __ballot_sync(0xffffffffu, valid && s == 1);
    unsigned bv = __ballot_sync(0xffffffffu, valid);
    if ((tid & 31) == 0) {
        atomicAdd(&cnt[1], __popc(bf));
        atomicAdd(&cnt[0], __popc(bv) - __popc(bf));
    }

    #pragma unroll
    for (int i = 0; i < 10; ++i) {
        // replicate reference binning bit pattern: floor((x-mn)/width * 10), clip
        float f = (x[i] - smn[i]) / swid[i] * 10.0f;
        int idx = (int)floorf(f);
        idx = min(max(idx, 0), 9);
        int key = valid ? (s * 10 + idx) : (32 + (tid & 31));  // invalid lanes unique
        unsigned mask = __match_any_sync(0xffffffffu, key);
        if (valid && (tid & 31) == (__ffs(mask) - 1)) {
            atomicAdd(&hist[(s * 10 + i) * 10 + idx], __popc(mask));
        }
    }

    __syncthreads();
    if (tid < 200 && hist[tid] != 0) atomicAdd(&g_hist[tid], hist[tid]);
    if (tid < 2) atomicAdd(&g_cnt[tid], cnt[tid]);
}

// ---------------------------------------------------------------------------
// k_final: 100-bin KLD parallel over 128 threads, fp32 __logf (MUFU).
// ---------------------------------------------------------------------------
__global__ void __launch_bounds__(128) k_final(float* __restrict__ out, int B) {
    __shared__ float wred[4];
    int tid = threadIdx.x;

    float mc = g_cnt[0] > 0 ? (float)g_cnt[0] : 1.0f;
    float fc = g_cnt[1] > 0 ? (float)g_cnt[1] : 1.0f;

    float term = 0.f;
    if (tid < 100) {
        float p = (float)g_hist[tid]       / mc;
        float q = (float)g_hist[100 + tid] / fc;
        if (p > 0.f && q > 0.f) term = p * __logf(p / q);
    }
    #pragma unroll
    for (int o = 16; o; o >>= 1) term += __shfl_down_sync(0xffffffffu, term, o);
    if ((tid & 31) == 0) wred[tid >> 5] = term;
    __syncthreads();

    if (tid == 0) {
        float kld = wred[0] + wred[1] + wred[2] + wred[3];
        float mse = (float)(g_mse_sum / (double)B);
        float ce  = (float)(g_ce_sum  / (double)B);
        float ak  = 0.5f * kld;                 // alpha = RATIO_KLD = 0.5
        float multi = 0.5f * (mse + ce) + ak;   // (1-alpha)*(mse+ce) + alpha*kld
        out[0] = multi;
        out[1] = mse;
        out[2] = ce;
        out[3] = ak;
    }
}

extern "C" void kernel_launch(void* const* d_in, const int* in_sizes, int n_in,
                              void* d_out, int out_size) {
    (void)n_in; (void)out_size;
    const float* enc = (const float*)d_in[0];  // data_encoded [B,12]
    const float* dec = (const float*)d_in[1];  // data_decoded [B,99]
    const float* tru = (const float*)d_in[2];  // data_true    [B,99]
    // d_in[3] = label_true (unused), d_in[4] = batch_size (unused; derive B)
    int B = in_sizes[1] / NC;

    k_init<<<1, 256>>>();
    int tiles = (B + TR - 1) / TR;
    k_main<<<tiles, 256>>>(dec, tru, enc, B);
    int hb = (B + 255) / 256;
    k_hist<<<hb, 256>>>(enc, B);
    k_final<<<1, 128>>>((float*)d_out, B);
}